// round 15
// baseline (speedup 1.0000x reference)
#include <cuda_runtime.h>
#include <cuda_fp16.h>
#include <cstdint>
#include <cstddef>

// R13: identical to R12 (never measured — container infra failure); see analysis.

#define LOG2E 1.4426950408889634f
#define LN2f  0.6931471805599453f
#define NEGV  -100.0f
#define SBITS 20.0f        // emission table pre-scale = 2^20
#define SINTF 20.0f
#define CLN   (20.0f * 0.6931471805599453f)

#define T_LEN 1024
#define V_N   8000
#define TPB   256
#define WPB   8            // warps (=sequences) per block

// smem layout (bytes)
#define OFF_BT 0
#define OS_WST (8 * 36)                           // floats per (warp,state) quarter-tile
#define OFF_OS (V_N * 8)                          // 64,000
#define SMEMSZ (OFF_OS + WPB * 4 * OS_WST * 4)    // 64,000 + 36,864 = 100,864 B

// -------- device scratch (static allocation only) ---------------------------
__device__ __align__(16) ushort4 g_Bh4[V_N];  // fp16 emission probs * 2^20
__device__ float g_par[16];  // [0..3] pi_log2, [4..7] pi_prob, [8..11] A0p, [12..15] A1p
__device__ float g_pm[4][8], g_ps[4][8];
__device__ float g_lse[4];

// ---------------------------- prep kernels ----------------------------------
__global__ void prep1(const float* __restrict__ init_B) {
    __shared__ float red[256];
    int b = blockIdx.x, s = b >> 3, sl = b & 7;
    const float* row = init_B + (size_t)s * V_N + sl * 1000;
    int tid = threadIdx.x;
    float mx = -1e30f;
    for (int i = tid; i < 1000; i += 256) mx = fmaxf(mx, row[i]);
    red[tid] = mx; __syncthreads();
    for (int o = 128; o; o >>= 1) {
        if (tid < o) red[tid] = fmaxf(red[tid], red[tid + o]);
        __syncthreads();
    }
    mx = red[0]; __syncthreads();
    float sm = 0.f;
    for (int i = tid; i < 1000; i += 256) sm += expf(row[i] - mx);
    red[tid] = sm; __syncthreads();
    for (int o = 128; o; o >>= 1) {
        if (tid < o) red[tid] += red[tid + o];
        __syncthreads();
    }
    if (tid == 0) { g_pm[s][sl] = mx; g_ps[s][sl] = red[0]; }
}

__global__ void prep2(const float* __restrict__ init_pi,
                      const float* __restrict__ init_A) {
    if (threadIdx.x != 0) return;
    for (int s = 0; s < 4; ++s) {       // deterministic fixed-order LSE merge
        float M = g_pm[s][0];
        for (int i = 1; i < 8; ++i) M = fmaxf(M, g_pm[s][i]);
        float S = 0.f;
        for (int i = 0; i < 8; ++i) S += g_ps[s][i] * expf(g_pm[s][i] - M);
        g_lse[s] = M + logf(S);
    }
    float x[4];
    const float pim[4] = {0.f, NEGV, NEGV, 0.f};
    float mx = -1e30f;
    for (int i = 0; i < 4; ++i) { x[i] = init_pi[i] + pim[i]; mx = fmaxf(mx, x[i]); }
    float smv = 0.f;
    for (int i = 0; i < 4; ++i) smv += expf(x[i] - mx);
    float lse = mx + logf(smv);
    for (int i = 0; i < 4; ++i) {
        float pl = fmaxf(x[i] - lse, NEGV) * LOG2E;
        g_par[i] = pl;
        g_par[4 + i] = exp2f(pl);
    }
    const int pat[16] = {0,1,1,0, 0,1,1,0, 1,0,0,1, 1,0,0,1};
    float Ap[16];
    for (int r = 0; r < 4; ++r) {
        float y[4]; float m2 = -1e30f;
        for (int j = 0; j < 4; ++j) {
            y[j] = init_A[r * 4 + j] + (pat[r * 4 + j] ? 0.f : NEGV);
            m2 = fmaxf(m2, y[j]);
        }
        float s2 = 0.f;
        for (int j = 0; j < 4; ++j) s2 += expf(y[j] - m2);
        float l2 = m2 + logf(s2);
        for (int j = 0; j < 4; ++j)
            Ap[r * 4 + j] = expf(fmaxf(y[j] - l2, NEGV));
    }
    // col s allowed preds: s0<-{2,3}, s1<-{0,1}, s2<-{0,1}, s3<-{2,3}
    g_par[8]  = Ap[2*4+0]; g_par[12] = Ap[3*4+0];
    g_par[9]  = Ap[0*4+1]; g_par[13] = Ap[1*4+1];
    g_par[10] = Ap[0*4+2]; g_par[14] = Ap[1*4+2];
    g_par[11] = Ap[2*4+3]; g_par[15] = Ap[3*4+3];
}

__global__ void prep3(const float* __restrict__ init_B) {
    int b = blockIdx.x, s = b >> 3, sl = b & 7;
    const float* row = init_B + (size_t)s * V_N;
    float lse = g_lse[s];
    for (int i = threadIdx.x + sl * 1000; i < (sl + 1) * 1000; i += 256) {
        float lb2 = fmaxf(row[i] - lse, NEGV) * LOG2E;
        float pv  = exp2f(lb2 + SBITS);
        ((unsigned short*)&g_Bh4[i])[s] = __half_as_ushort(__float2half_rn(pv));
    }
}

// ---------------------------- main kernel -----------------------------------
__device__ __forceinline__ float flg2(float x) {
    float r; asm("lg2.approx.ftz.f32 %0, %1;" : "=f"(r) : "f"(x)); return r;
}

__device__ __forceinline__ float4 emis(const uint2* __restrict__ bt, int y) {
    uint2 u = bt[y];
    float2 f0 = __half22float2(*reinterpret_cast<__half2*>(&u.x));
    float2 f1 = __half22float2(*reinterpret_cast<__half2*>(&u.y));
    return make_float4(f0.x, f0.y, f1.x, f1.y);
}

__device__ __forceinline__ void rescale16f(float* p, float& E) {
    float mx = p[0];
#pragma unroll
    for (int k = 1; k < 16; ++k) mx = fmaxf(mx, p[k]);
    int ex = (int)((__float_as_uint(mx) >> 23) & 255u) - 127;
    float sc = __uint_as_float((unsigned)(127 - ex) << 23);
#pragma unroll
    for (int k = 0; k < 16; ++k) p[k] *= sc;
    E += (float)ex;
}

#define YIDX(k) ((int)((ypk[(k) >> 1] >> (((k) & 1) * 16)) & 0xFFFFu))

__global__ void __launch_bounds__(TPB, 2)
hmm_kernel(const int* __restrict__ Y, const float* __restrict__ mask,
           float* __restrict__ out) {
    extern __shared__ __align__(16) char raw[];
    uint2* bt  = reinterpret_cast<uint2*>(raw + OFF_BT);
    float* osA = reinterpret_cast<float*>(raw + OFF_OS);

    const int tid = threadIdx.x, w = tid >> 5, lane = tid & 31;
    float* osw = osA + w * 4 * OS_WST;           // my warp's 4 quarter-tiles

    // ---- stage fp16 emission table (uint4 = 2 entries per iter) ----
    {
        const uint4* src = reinterpret_cast<const uint4*>(g_Bh4);
        uint4* dst = reinterpret_cast<uint4*>(raw + OFF_BT);
        for (int i = tid; i < V_N / 2; i += TPB) dst[i] = src[i];
    }
    __syncthreads();

    const int seq = blockIdx.x * WPB + w;

    // ---- COALESCED input load, redistributed via my warp's staging smem ----
    // Y: 8 coalesced LDG.128 -> u16-pair words -> pad-17 stash -> per-lane regs
    unsigned ypk[16];
    unsigned mbits = 0;
    {
        unsigned* stash = reinterpret_cast<unsigned*>(osw);            // 544 words
        unsigned char* mstash = reinterpret_cast<unsigned char*>(osw) + 2176; // 256 B
        const int4*   y4 = (const int4*)(Y    + (size_t)seq * T_LEN);
        const float4* m4 = (const float4*)(mask + (size_t)seq * T_LEN);
#pragma unroll
        for (int g = 0; g < 8; ++g) {
            int4 yv = y4[g * 32 + lane];
            float4 mv = m4[g * 32 + lane];
            unsigned w0 = (unsigned)yv.x | ((unsigned)yv.y << 16);
            unsigned w1 = (unsigned)yv.z | ((unsigned)yv.w << 16);
            int wi = g * 64 + lane * 2;           // packed-word index 0..511
            int ai = (wi >> 4) * 17 + (wi & 15);  // pad-17: conflict-free gather
            stash[ai] = w0; stash[ai + 1] = w1;
            unsigned b = (mv.x > 0.5f ? 1u : 0u) | (mv.y > 0.5f ? 2u : 0u)
                       | (mv.z > 0.5f ? 4u : 0u) | (mv.w > 0.5f ? 8u : 0u);
            mstash[g * 32 + lane] = (unsigned char)b;
        }
        __syncwarp();
#pragma unroll
        for (int k = 0; k < 16; ++k)
            ypk[k] = stash[lane * 17 + k];        // conflict-free (17 coprime 32)
        uint2 mb = *reinterpret_cast<const uint2*>(mstash + lane * 8);
#pragma unroll
        for (int k = 0; k < 4; ++k) {
            mbits |= ((mb.x >> (8 * k)) & 0xFu) << (4 * k);
            mbits |= ((mb.y >> (8 * k)) & 0xFu) << (16 + 4 * k);
        }
        __syncwarp();
    }
    if (lane == 0) mbits &= ~1u;      // t=0 lives in alpha0, never a transition

    const float B00 = g_par[8],  B01 = g_par[9],  B02 = g_par[10], B03 = g_par[11];
    const float B10 = g_par[12], B11 = g_par[13], B12 = g_par[14], B13 = g_par[15];

    // ================= pass 1: chunk transfer matrix =================
    float p[16];
#pragma unroll
    for (int k = 0; k < 16; ++k) p[k] = (k % 5 == 0) ? 1.f : 0.f;   // identity
    float E = 0.f;
    {
        float4 e = emis(bt, YIDX(0));
#pragma unroll
        for (int j = 0; j < 32; ++j) {
            float4 ec = e;
            if (j < 31) e = emis(bt, YIDX(j + 1));   // prefetch off the p-chain
            bool mk = (mbits >> j) & 1u;
            float c00 = B00*ec.x, c10 = B10*ec.x;
            float c01 = B01*ec.y, c11 = B11*ec.y;
            float c02 = B02*ec.z, c12 = B12*ec.z;
            float c03 = B03*ec.w, c13 = B13*ec.w;
            float n[16];
#pragma unroll
            for (int r = 0; r < 4; ++r) {
                float a0 = p[r*4+0], a1 = p[r*4+1], a2 = p[r*4+2], a3 = p[r*4+3];
                n[r*4+0] = fmaf(a3, c10, a2 * c00);
                n[r*4+1] = fmaf(a1, c11, a0 * c01);
                n[r*4+2] = fmaf(a1, c12, a0 * c02);
                n[r*4+3] = fmaf(a3, c13, a2 * c03);
            }
#pragma unroll
            for (int k = 0; k < 16; ++k) p[k] = mk ? n[k] : p[k];
            if ((j & 7) == 7) rescale16f(p, E);
        }
        E -= SINTF * (float)__popc(mbits);   // exact: integers < 2^24
    }

    // ================= pass 2: Kogge-Stone inclusive scan =================
#pragma unroll
    for (int d = 1; d < 32; d <<= 1) {
        float q[16];
#pragma unroll
        for (int k = 0; k < 16; ++k) q[k] = __shfl_up_sync(0xffffffffu, p[k], d);
        float Eq = __shfl_up_sync(0xffffffffu, E, d);
        if (lane >= d) {
            float n[16];
#pragma unroll
            for (int r = 0; r < 4; ++r)
#pragma unroll
                for (int s = 0; s < 4; ++s)
                    n[r*4+s] = fmaf(q[r*4+3], p[12+s],
                               fmaf(q[r*4+2], p[8+s],
                               fmaf(q[r*4+1], p[4+s], q[r*4+0] * p[s])));
#pragma unroll
            for (int k = 0; k < 16; ++k) p[k] = n[k];
            E += Eq;
        }
        rescale16f(p, E);         // unconditional renorm, valid for all lanes
    }
    // exclusive shift: H_i = G_0 .. G_{i-1} (reuse p as h)
#pragma unroll
    for (int k = 0; k < 16; ++k) p[k] = __shfl_up_sync(0xffffffffu, p[k], 1);
    E = __shfl_up_sync(0xffffffffu, E, 1);
    if (lane == 0) {
#pragma unroll
        for (int k = 0; k < 16; ++k) p[k] = (k % 5 == 0) ? 1.f : 0.f;
        E = 0.f;
    }

    // ---- starting alpha for my chunk: A_i = alpha0 · H_i ----
    int    y0 = __shfl_sync(0xffffffffu, YIDX(0), 0);
    float4 e0 = emis(bt, y0);
    float al0, al1, al2, al3;
    {
        float a00 = g_par[4] * e0.x, a01 = g_par[5] * e0.y;
        float a02 = g_par[6] * e0.z, a03 = g_par[7] * e0.w;
        al0 = fmaf(a03, p[12+0], fmaf(a02, p[8+0], fmaf(a01, p[4+0], a00 * p[0])));
        al1 = fmaf(a03, p[12+1], fmaf(a02, p[8+1], fmaf(a01, p[4+1], a00 * p[1])));
        al2 = fmaf(a03, p[12+2], fmaf(a02, p[8+2], fmaf(a01, p[4+2], a00 * p[2])));
        al3 = fmaf(a03, p[12+3], fmaf(a02, p[8+3], fmaf(a01, p[4+3], a00 * p[3])));
    }
    E -= SINTF;
    {
        float mx = fmaxf(fmaxf(al0, al1), fmaxf(al2, al3));
        int ex = (int)((__float_as_uint(mx) >> 23) & 255u) - 127;
        float sc = __uint_as_float((unsigned)(127 - ex) << 23);
        al0 *= sc; al1 *= sc; al2 *= sc; al3 *= sc; E += (float)ex;
    }

    // ==== pass 3: replay in four 8-step quarters, staged vectorized flush ===
    float* os0 = osw + 0 * OS_WST;
    float* os1 = osw + 1 * OS_WST;
    float* os2 = osw + 2 * OS_WST;
    float* os3 = osw + 3 * OS_WST;

    float EfL = E * LN2f;             // running log-scale offset
    float4 e = emis(bt, YIDX(0));
#pragma unroll
    for (int qt = 0; qt < 4; ++qt) {
#pragma unroll
        for (int u = 0; u < 8; ++u) {
            const int j = qt * 8 + u;
            float4 ec = e;
            if (j < 31) e = emis(bt, YIDX(j + 1));
            bool mk = (mbits >> j) & 1u;
            float c00 = B00*ec.x, c10 = B10*ec.x;
            float c01 = B01*ec.y, c11 = B11*ec.y;
            float c02 = B02*ec.z, c12 = B12*ec.z;
            float c03 = B03*ec.w, c13 = B13*ec.w;
            float n0 = fmaf(al3, c10, al2 * c00);
            float n1 = fmaf(al1, c11, al0 * c01);
            float n2 = fmaf(al1, c12, al0 * c02);
            float n3 = fmaf(al3, c13, al2 * c03);
            al0 = mk ? n0 : al0;  al1 = mk ? n1 : al1;
            al2 = mk ? n2 : al2;  al3 = mk ? n3 : al3;
            EfL = mk ? EfL - CLN : EfL;
            float b0 = fmaf(flg2(al0), LN2f, EfL);
            float b1 = fmaf(flg2(al1), LN2f, EfL);
            float b2 = fmaf(flg2(al2), LN2f, EfL);
            float b3 = fmaf(flg2(al3), LN2f, EfL);
            if (qt == 0 && u == 0 && lane == 0) {
                // exact t=0 (pi-masked states underflow in prob domain)
                b0 = (g_par[0] + flg2(e0.x) - SBITS) * LN2f;
                b1 = (g_par[1] + flg2(e0.y) - SBITS) * LN2f;
                b2 = (g_par[2] + flg2(e0.z) - SBITS) * LN2f;
                b3 = (g_par[3] + flg2(e0.w) - SBITS) * LN2f;
            }
            int a = u * 36 + lane;                     // conflict-free STS
            os0[a] = b0;  os1[a] = b1;  os2[a] = b2;  os3[a] = b3;
            if (u == 7) {
                float mx = fmaxf(fmaxf(al0, al1), fmaxf(al2, al3));
                int ex = (int)((__float_as_uint(mx) >> 23) & 255u) - 127;
                float sc = __uint_as_float((unsigned)(127 - ex) << 23);
                al0 *= sc; al1 *= sc; al2 *= sc; al3 *= sc;
                EfL = fmaf((float)ex, LN2f, EfL);
            }
        }
        __syncwarp();
        // vectorized flush: lane (m=lane&1, cb=lane>>1), cols cb and cb+16
        {
            const int m = lane & 1, cb = lane >> 1, k0 = m * 4;
#pragma unroll
            for (int i = 0; i < 2; ++i) {
                const int col = cb + i * 16;
#pragma unroll
                for (int s = 0; s < 4; ++s) {
                    const float* src = osw + s * OS_WST;
                    float4 v;
                    v.x = src[(k0 + 0) * 36 + col];    // conflict-free LDS
                    v.y = src[(k0 + 1) * 36 + col];
                    v.z = src[(k0 + 2) * 36 + col];
                    v.w = src[(k0 + 3) * 36 + col];
                    *reinterpret_cast<float4*>(
                        out + (size_t)(seq * 4 + s) * T_LEN + col * 32 + qt * 8 + k0) = v;
                }
            }
        }
        __syncwarp();
    }
}

// ---------------------------- launch ----------------------------------------
extern "C" void kernel_launch(void* const* d_in, const int* in_sizes, int n_in,
                              void* d_out, int out_size) {
    const int*   Y    = (const int*)d_in[0];
    const float* mask = (const float*)d_in[1];
    const float* pi   = (const float*)d_in[2];
    const float* A    = (const float*)d_in[3];
    const float* B    = (const float*)d_in[4];
    float* out = (float*)d_out;

    int N = in_sizes[0] / T_LEN;          // 8192

    cudaFuncSetAttribute(hmm_kernel,
                         cudaFuncAttributeMaxDynamicSharedMemorySize, SMEMSZ);

    prep1<<<32, 256>>>(B);
    prep2<<<1, 32>>>(pi, A);
    prep3<<<32, 256>>>(B);
    hmm_kernel<<<N / WPB, TPB, SMEMSZ>>>(Y, mask, out);
}

// round 16
// speedup vs baseline: 1.0227x; 1.0227x over previous
#include <cuda_runtime.h>
#include <cuda_fp16.h>
#include <cstdint>
#include <cstddef>

// R13: identical to R12 (never measured — container infra failure); see analysis.

#define LOG2E 1.4426950408889634f
#define LN2f  0.6931471805599453f
#define NEGV  -100.0f
#define SBITS 20.0f        // emission table pre-scale = 2^20
#define SINTF 20.0f
#define CLN   (20.0f * 0.6931471805599453f)

#define T_LEN 1024
#define V_N   8000
#define TPB   256
#define WPB   8            // warps (=sequences) per block

// smem layout (bytes)
#define OFF_BT 0
#define OS_WST (8 * 36)                           // floats per (warp,state) quarter-tile
#define OFF_OS (V_N * 8)                          // 64,000
#define SMEMSZ (OFF_OS + WPB * 4 * OS_WST * 4)    // 64,000 + 36,864 = 100,864 B

// -------- device scratch (static allocation only) ---------------------------
__device__ __align__(16) ushort4 g_Bh4[V_N];  // fp16 emission probs * 2^20
__device__ float g_par[16];  // [0..3] pi_log2, [4..7] pi_prob, [8..11] A0p, [12..15] A1p
__device__ float g_pm[4][8], g_ps[4][8];
__device__ float g_lse[4];

// ---------------------------- prep kernels ----------------------------------
__global__ void prep1(const float* __restrict__ init_B) {
    __shared__ float red[256];
    int b = blockIdx.x, s = b >> 3, sl = b & 7;
    const float* row = init_B + (size_t)s * V_N + sl * 1000;
    int tid = threadIdx.x;
    float mx = -1e30f;
    for (int i = tid; i < 1000; i += 256) mx = fmaxf(mx, row[i]);
    red[tid] = mx; __syncthreads();
    for (int o = 128; o; o >>= 1) {
        if (tid < o) red[tid] = fmaxf(red[tid], red[tid + o]);
        __syncthreads();
    }
    mx = red[0]; __syncthreads();
    float sm = 0.f;
    for (int i = tid; i < 1000; i += 256) sm += expf(row[i] - mx);
    red[tid] = sm; __syncthreads();
    for (int o = 128; o; o >>= 1) {
        if (tid < o) red[tid] += red[tid + o];
        __syncthreads();
    }
    if (tid == 0) { g_pm[s][sl] = mx; g_ps[s][sl] = red[0]; }
}

__global__ void prep2(const float* __restrict__ init_pi,
                      const float* __restrict__ init_A) {
    if (threadIdx.x != 0) return;
    for (int s = 0; s < 4; ++s) {       // deterministic fixed-order LSE merge
        float M = g_pm[s][0];
        for (int i = 1; i < 8; ++i) M = fmaxf(M, g_pm[s][i]);
        float S = 0.f;
        for (int i = 0; i < 8; ++i) S += g_ps[s][i] * expf(g_pm[s][i] - M);
        g_lse[s] = M + logf(S);
    }
    float x[4];
    const float pim[4] = {0.f, NEGV, NEGV, 0.f};
    float mx = -1e30f;
    for (int i = 0; i < 4; ++i) { x[i] = init_pi[i] + pim[i]; mx = fmaxf(mx, x[i]); }
    float smv = 0.f;
    for (int i = 0; i < 4; ++i) smv += expf(x[i] - mx);
    float lse = mx + logf(smv);
    for (int i = 0; i < 4; ++i) {
        float pl = fmaxf(x[i] - lse, NEGV) * LOG2E;
        g_par[i] = pl;
        g_par[4 + i] = exp2f(pl);
    }
    const int pat[16] = {0,1,1,0, 0,1,1,0, 1,0,0,1, 1,0,0,1};
    float Ap[16];
    for (int r = 0; r < 4; ++r) {
        float y[4]; float m2 = -1e30f;
        for (int j = 0; j < 4; ++j) {
            y[j] = init_A[r * 4 + j] + (pat[r * 4 + j] ? 0.f : NEGV);
            m2 = fmaxf(m2, y[j]);
        }
        float s2 = 0.f;
        for (int j = 0; j < 4; ++j) s2 += expf(y[j] - m2);
        float l2 = m2 + logf(s2);
        for (int j = 0; j < 4; ++j)
            Ap[r * 4 + j] = expf(fmaxf(y[j] - l2, NEGV));
    }
    // col s allowed preds: s0<-{2,3}, s1<-{0,1}, s2<-{0,1}, s3<-{2,3}
    g_par[8]  = Ap[2*4+0]; g_par[12] = Ap[3*4+0];
    g_par[9]  = Ap[0*4+1]; g_par[13] = Ap[1*4+1];
    g_par[10] = Ap[0*4+2]; g_par[14] = Ap[1*4+2];
    g_par[11] = Ap[2*4+3]; g_par[15] = Ap[3*4+3];
}

__global__ void prep3(const float* __restrict__ init_B) {
    int b = blockIdx.x, s = b >> 3, sl = b & 7;
    const float* row = init_B + (size_t)s * V_N;
    float lse = g_lse[s];
    for (int i = threadIdx.x + sl * 1000; i < (sl + 1) * 1000; i += 256) {
        float lb2 = fmaxf(row[i] - lse, NEGV) * LOG2E;
        float pv  = exp2f(lb2 + SBITS);
        ((unsigned short*)&g_Bh4[i])[s] = __half_as_ushort(__float2half_rn(pv));
    }
}

// ---------------------------- main kernel -----------------------------------
__device__ __forceinline__ float flg2(float x) {
    float r; asm("lg2.approx.ftz.f32 %0, %1;" : "=f"(r) : "f"(x)); return r;
}

__device__ __forceinline__ float4 emis(const uint2* __restrict__ bt, int y) {
    uint2 u = bt[y];
    float2 f0 = __half22float2(*reinterpret_cast<__half2*>(&u.x));
    float2 f1 = __half22float2(*reinterpret_cast<__half2*>(&u.y));
    return make_float4(f0.x, f0.y, f1.x, f1.y);
}

__device__ __forceinline__ void rescale16f(float* p, float& E) {
    float mx = p[0];
#pragma unroll
    for (int k = 1; k < 16; ++k) mx = fmaxf(mx, p[k]);
    int ex = (int)((__float_as_uint(mx) >> 23) & 255u) - 127;
    float sc = __uint_as_float((unsigned)(127 - ex) << 23);
#pragma unroll
    for (int k = 0; k < 16; ++k) p[k] *= sc;
    E += (float)ex;
}

#define YIDX(k) ((int)((ypk[(k) >> 1] >> (((k) & 1) * 16)) & 0xFFFFu))

__global__ void __launch_bounds__(TPB, 2)
hmm_kernel(const int* __restrict__ Y, const float* __restrict__ mask,
           float* __restrict__ out) {
    extern __shared__ __align__(16) char raw[];
    uint2* bt  = reinterpret_cast<uint2*>(raw + OFF_BT);
    float* osA = reinterpret_cast<float*>(raw + OFF_OS);

    const int tid = threadIdx.x, w = tid >> 5, lane = tid & 31;
    float* osw = osA + w * 4 * OS_WST;           // my warp's 4 quarter-tiles

    // ---- stage fp16 emission table (uint4 = 2 entries per iter) ----
    {
        const uint4* src = reinterpret_cast<const uint4*>(g_Bh4);
        uint4* dst = reinterpret_cast<uint4*>(raw + OFF_BT);
        for (int i = tid; i < V_N / 2; i += TPB) dst[i] = src[i];
    }
    __syncthreads();

    const int seq = blockIdx.x * WPB + w;

    // ---- COALESCED input load, redistributed via my warp's staging smem ----
    // Y: 8 coalesced LDG.128 -> u16-pair words -> pad-17 stash -> per-lane regs
    unsigned ypk[16];
    unsigned mbits = 0;
    {
        unsigned* stash = reinterpret_cast<unsigned*>(osw);            // 544 words
        unsigned char* mstash = reinterpret_cast<unsigned char*>(osw) + 2176; // 256 B
        const int4*   y4 = (const int4*)(Y    + (size_t)seq * T_LEN);
        const float4* m4 = (const float4*)(mask + (size_t)seq * T_LEN);
#pragma unroll
        for (int g = 0; g < 8; ++g) {
            int4 yv = y4[g * 32 + lane];
            float4 mv = m4[g * 32 + lane];
            unsigned w0 = (unsigned)yv.x | ((unsigned)yv.y << 16);
            unsigned w1 = (unsigned)yv.z | ((unsigned)yv.w << 16);
            int wi = g * 64 + lane * 2;           // packed-word index 0..511
            int ai = (wi >> 4) * 17 + (wi & 15);  // pad-17: conflict-free gather
            stash[ai] = w0; stash[ai + 1] = w1;
            unsigned b = (mv.x > 0.5f ? 1u : 0u) | (mv.y > 0.5f ? 2u : 0u)
                       | (mv.z > 0.5f ? 4u : 0u) | (mv.w > 0.5f ? 8u : 0u);
            mstash[g * 32 + lane] = (unsigned char)b;
        }
        __syncwarp();
#pragma unroll
        for (int k = 0; k < 16; ++k)
            ypk[k] = stash[lane * 17 + k];        // conflict-free (17 coprime 32)
        uint2 mb = *reinterpret_cast<const uint2*>(mstash + lane * 8);
#pragma unroll
        for (int k = 0; k < 4; ++k) {
            mbits |= ((mb.x >> (8 * k)) & 0xFu) << (4 * k);
            mbits |= ((mb.y >> (8 * k)) & 0xFu) << (16 + 4 * k);
        }
        __syncwarp();
    }
    if (lane == 0) mbits &= ~1u;      // t=0 lives in alpha0, never a transition

    const float B00 = g_par[8],  B01 = g_par[9],  B02 = g_par[10], B03 = g_par[11];
    const float B10 = g_par[12], B11 = g_par[13], B12 = g_par[14], B13 = g_par[15];

    // ================= pass 1: chunk transfer matrix =================
    float p[16];
#pragma unroll
    for (int k = 0; k < 16; ++k) p[k] = (k % 5 == 0) ? 1.f : 0.f;   // identity
    float E = 0.f;
    {
        float4 e = emis(bt, YIDX(0));
#pragma unroll
        for (int j = 0; j < 32; ++j) {
            float4 ec = e;
            if (j < 31) e = emis(bt, YIDX(j + 1));   // prefetch off the p-chain
            bool mk = (mbits >> j) & 1u;
            float c00 = B00*ec.x, c10 = B10*ec.x;
            float c01 = B01*ec.y, c11 = B11*ec.y;
            float c02 = B02*ec.z, c12 = B12*ec.z;
            float c03 = B03*ec.w, c13 = B13*ec.w;
            float n[16];
#pragma unroll
            for (int r = 0; r < 4; ++r) {
                float a0 = p[r*4+0], a1 = p[r*4+1], a2 = p[r*4+2], a3 = p[r*4+3];
                n[r*4+0] = fmaf(a3, c10, a2 * c00);
                n[r*4+1] = fmaf(a1, c11, a0 * c01);
                n[r*4+2] = fmaf(a1, c12, a0 * c02);
                n[r*4+3] = fmaf(a3, c13, a2 * c03);
            }
#pragma unroll
            for (int k = 0; k < 16; ++k) p[k] = mk ? n[k] : p[k];
            if ((j & 7) == 7) rescale16f(p, E);
        }
        E -= SINTF * (float)__popc(mbits);   // exact: integers < 2^24
    }

    // ================= pass 2: Kogge-Stone inclusive scan =================
#pragma unroll
    for (int d = 1; d < 32; d <<= 1) {
        float q[16];
#pragma unroll
        for (int k = 0; k < 16; ++k) q[k] = __shfl_up_sync(0xffffffffu, p[k], d);
        float Eq = __shfl_up_sync(0xffffffffu, E, d);
        if (lane >= d) {
            float n[16];
#pragma unroll
            for (int r = 0; r < 4; ++r)
#pragma unroll
                for (int s = 0; s < 4; ++s)
                    n[r*4+s] = fmaf(q[r*4+3], p[12+s],
                               fmaf(q[r*4+2], p[8+s],
                               fmaf(q[r*4+1], p[4+s], q[r*4+0] * p[s])));
#pragma unroll
            for (int k = 0; k < 16; ++k) p[k] = n[k];
            E += Eq;
        }
        rescale16f(p, E);         // unconditional renorm, valid for all lanes
    }
    // exclusive shift: H_i = G_0 .. G_{i-1} (reuse p as h)
#pragma unroll
    for (int k = 0; k < 16; ++k) p[k] = __shfl_up_sync(0xffffffffu, p[k], 1);
    E = __shfl_up_sync(0xffffffffu, E, 1);
    if (lane == 0) {
#pragma unroll
        for (int k = 0; k < 16; ++k) p[k] = (k % 5 == 0) ? 1.f : 0.f;
        E = 0.f;
    }

    // ---- starting alpha for my chunk: A_i = alpha0 · H_i ----
    int    y0 = __shfl_sync(0xffffffffu, YIDX(0), 0);
    float4 e0 = emis(bt, y0);
    float al0, al1, al2, al3;
    {
        float a00 = g_par[4] * e0.x, a01 = g_par[5] * e0.y;
        float a02 = g_par[6] * e0.z, a03 = g_par[7] * e0.w;
        al0 = fmaf(a03, p[12+0], fmaf(a02, p[8+0], fmaf(a01, p[4+0], a00 * p[0])));
        al1 = fmaf(a03, p[12+1], fmaf(a02, p[8+1], fmaf(a01, p[4+1], a00 * p[1])));
        al2 = fmaf(a03, p[12+2], fmaf(a02, p[8+2], fmaf(a01, p[4+2], a00 * p[2])));
        al3 = fmaf(a03, p[12+3], fmaf(a02, p[8+3], fmaf(a01, p[4+3], a00 * p[3])));
    }
    E -= SINTF;
    {
        float mx = fmaxf(fmaxf(al0, al1), fmaxf(al2, al3));
        int ex = (int)((__float_as_uint(mx) >> 23) & 255u) - 127;
        float sc = __uint_as_float((unsigned)(127 - ex) << 23);
        al0 *= sc; al1 *= sc; al2 *= sc; al3 *= sc; E += (float)ex;
    }

    // ==== pass 3: replay in four 8-step quarters, staged vectorized flush ===
    float* os0 = osw + 0 * OS_WST;
    float* os1 = osw + 1 * OS_WST;
    float* os2 = osw + 2 * OS_WST;
    float* os3 = osw + 3 * OS_WST;

    float EfL = E * LN2f;             // running log-scale offset
    float4 e = emis(bt, YIDX(0));
#pragma unroll
    for (int qt = 0; qt < 4; ++qt) {
#pragma unroll
        for (int u = 0; u < 8; ++u) {
            const int j = qt * 8 + u;
            float4 ec = e;
            if (j < 31) e = emis(bt, YIDX(j + 1));
            bool mk = (mbits >> j) & 1u;
            float c00 = B00*ec.x, c10 = B10*ec.x;
            float c01 = B01*ec.y, c11 = B11*ec.y;
            float c02 = B02*ec.z, c12 = B12*ec.z;
            float c03 = B03*ec.w, c13 = B13*ec.w;
            float n0 = fmaf(al3, c10, al2 * c00);
            float n1 = fmaf(al1, c11, al0 * c01);
            float n2 = fmaf(al1, c12, al0 * c02);
            float n3 = fmaf(al3, c13, al2 * c03);
            al0 = mk ? n0 : al0;  al1 = mk ? n1 : al1;
            al2 = mk ? n2 : al2;  al3 = mk ? n3 : al3;
            EfL = mk ? EfL - CLN : EfL;
            float b0 = fmaf(flg2(al0), LN2f, EfL);
            float b1 = fmaf(flg2(al1), LN2f, EfL);
            float b2 = fmaf(flg2(al2), LN2f, EfL);
            float b3 = fmaf(flg2(al3), LN2f, EfL);
            if (qt == 0 && u == 0 && lane == 0) {
                // exact t=0 (pi-masked states underflow in prob domain)
                b0 = (g_par[0] + flg2(e0.x) - SBITS) * LN2f;
                b1 = (g_par[1] + flg2(e0.y) - SBITS) * LN2f;
                b2 = (g_par[2] + flg2(e0.z) - SBITS) * LN2f;
                b3 = (g_par[3] + flg2(e0.w) - SBITS) * LN2f;
            }
            int a = u * 36 + lane;                     // conflict-free STS
            os0[a] = b0;  os1[a] = b1;  os2[a] = b2;  os3[a] = b3;
            if (u == 7) {
                float mx = fmaxf(fmaxf(al0, al1), fmaxf(al2, al3));
                int ex = (int)((__float_as_uint(mx) >> 23) & 255u) - 127;
                float sc = __uint_as_float((unsigned)(127 - ex) << 23);
                al0 *= sc; al1 *= sc; al2 *= sc; al3 *= sc;
                EfL = fmaf((float)ex, LN2f, EfL);
            }
        }
        __syncwarp();
        // vectorized flush: lane (m=lane&1, cb=lane>>1), cols cb and cb+16
        {
            const int m = lane & 1, cb = lane >> 1, k0 = m * 4;
#pragma unroll
            for (int i = 0; i < 2; ++i) {
                const int col = cb + i * 16;
#pragma unroll
                for (int s = 0; s < 4; ++s) {
                    const float* src = osw + s * OS_WST;
                    float4 v;
                    v.x = src[(k0 + 0) * 36 + col];    // conflict-free LDS
                    v.y = src[(k0 + 1) * 36 + col];
                    v.z = src[(k0 + 2) * 36 + col];
                    v.w = src[(k0 + 3) * 36 + col];
                    *reinterpret_cast<float4*>(
                        out + (size_t)(seq * 4 + s) * T_LEN + col * 32 + qt * 8 + k0) = v;
                }
            }
        }
        __syncwarp();
    }
}

// ---------------------------- launch ----------------------------------------
extern "C" void kernel_launch(void* const* d_in, const int* in_sizes, int n_in,
                              void* d_out, int out_size) {
    const int*   Y    = (const int*)d_in[0];
    const float* mask = (const float*)d_in[1];
    const float* pi   = (const float*)d_in[2];
    const float* A    = (const float*)d_in[3];
    const float* B    = (const float*)d_in[4];
    float* out = (float*)d_out;

    int N = in_sizes[0] / T_LEN;          // 8192

    cudaFuncSetAttribute(hmm_kernel,
                         cudaFuncAttributeMaxDynamicSharedMemorySize, SMEMSZ);

    prep1<<<32, 256>>>(B);
    prep2<<<1, 32>>>(pi, A);
    prep3<<<32, 256>>>(B);
    hmm_kernel<<<N / WPB, TPB, SMEMSZ>>>(Y, mask, out);
}